// round 15
// baseline (speedup 1.0000x reference)
#include <cuda_runtime.h>
#include <cuda_fp16.h>
#include <math_constants.h>
#include <cstdint>

#define NN 50000
#define EE 400000
#define BB 16
#define SCAN_E 1024
#define SCAN_NB ((NN + SCAN_E - 1) / SCAN_E)  // 49
#define GM ((NN + 127) / 128)                 // 391 M-tiles

typedef unsigned long long ull;

// ---------------- scratch (static device globals; no allocation) ----------------
__device__ __half g_h0h[NN * 64];   // h0 in fp16 (GEMM A operand)
__device__ __half g_hh [NN * 64];   // h  in fp16 (GEMM A operand)
__device__ float  g_h  [NN * 64];   // h  in fp32 (readout, last layer only)
__device__ __half g_wsh[128 * 256]; // W_src fp16
__device__ __half g_wdh[128 * 256]; // W_dst fp16
__device__ uint4  g_fsh[NN * 32];   // fs as fp16: 256 halves = 32 uint4 per node
__device__ float  g_fd [NN * 256];
__device__ float  g_cs [NN * 256];  // h0 @ W_src[64:] + b_src   (layer-invariant)
__device__ float  g_cd [NN * 256];  // h0 @ W_dst[64:] + b_dst
__device__ int    g_rowptr[NN + 1];
__device__ int    g_cursor[NN];
__device__ int    g_counts[NN];
__device__ int    g_col[EE];
__device__ int    g_bsum[SCAN_NB];
__device__ float  g_hg[BB * 64];

// ---------------- packed f32x2 helpers ----------------
__device__ __forceinline__ void fma2(ull& d, ull a, ull b) {
    asm("fma.rn.f32x2 %0, %1, %2, %0;" : "+l"(d) : "l"(a), "l"(b));
}
__device__ __forceinline__ ull dupf2(float v) {
    ull r; uint32_t u = __float_as_uint(v);
    asm("mov.b64 %0, {%1, %1};" : "=l"(r) : "r"(u));
    return r;
}
__device__ __forceinline__ ull packf2(float2 v) {
    ull r;
    asm("mov.b64 %0, {%1, %2};" : "=l"(r) : "f"(v.x), "f"(v.y));
    return r;
}
__device__ __forceinline__ float2 unpackf2(ull v) {
    float lo, hi;
    asm("mov.b64 {%0, %1}, %2;" : "=f"(lo), "=f"(hi) : "l"(v));
    return make_float2(lo, hi);
}

// ---- h0 = feat @ W_in + b_in (fp16 out) + zero counters + convert W to fp16 ----
__global__ void k_in(const float* __restrict__ feat, const float* __restrict__ Win,
                     const float* __restrict__ bin,
                     const float* __restrict__ Wsrc, const float* __restrict__ Wdst) {
    int idx = blockIdx.x * blockDim.x + threadIdx.x;
    if (idx < NN) g_counts[idx] = 0;
    if (idx < BB * 64) g_hg[idx] = 0.f;
    if (idx < 128 * 256) {
        g_wsh[idx] = __float2half(Wsrc[idx]);
        g_wdh[idx] = __float2half(Wdst[idx]);
    }
    if (idx >= NN * 64) return;
    int n = idx >> 6, d = idx & 63;
    float s = bin[d];
#pragma unroll
    for (int k = 0; k < 16; k++) s += feat[n * 16 + k] * Win[k * 64 + d];
    g_h0h[idx] = __float2half(s);
}

// ---------------- CSR build (keyed by dst) ----------------
__global__ void k_hist(const int* __restrict__ dst) {
    int e = blockIdx.x * blockDim.x + threadIdx.x;
    if (e < EE) atomicAdd(&g_counts[dst[e]], 1);
}

__global__ void k_scan1() {
    __shared__ int ws[8];
    int t = threadIdx.x, b = blockIdx.x;
    int base = b * SCAN_E + t * 4;
    int v0 = 0, v1 = 0, v2 = 0, v3 = 0;
    if (base + 0 < NN) v0 = g_counts[base + 0];
    if (base + 1 < NN) v1 = g_counts[base + 1];
    if (base + 2 < NN) v2 = g_counts[base + 2];
    if (base + 3 < NN) v3 = g_counts[base + 3];
    int s = v0 + v1 + v2 + v3;
    int lane = t & 31, wid = t >> 5;
    int x = s;
#pragma unroll
    for (int o = 1; o < 32; o <<= 1) {
        int u = __shfl_up_sync(0xffffffffu, x, o);
        if (lane >= o) x += u;
    }
    if (lane == 31) ws[wid] = x;
    __syncthreads();
    if (wid == 0 && lane < 8) {
        int w = ws[lane];
#pragma unroll
        for (int o = 1; o < 8; o <<= 1) {
            int u = __shfl_up_sync(0x000000ffu, w, o);
            if (lane >= o) w += u;
        }
        ws[lane] = w;
    }
    __syncthreads();
    int excl = (x - s) + (wid > 0 ? ws[wid - 1] : 0);
    int run = excl;
    if (base + 0 < NN) { g_rowptr[base + 0] = run; run += v0; }
    if (base + 1 < NN) { g_rowptr[base + 1] = run; run += v1; }
    if (base + 2 < NN) { g_rowptr[base + 2] = run; run += v2; }
    if (base + 3 < NN) { g_rowptr[base + 3] = run; run += v3; }
    if (t == blockDim.x - 1) g_bsum[b] = excl + s;
}

__global__ void k_scan3() {
    __shared__ int soff;
    int t = threadIdx.x, b = blockIdx.x;
    if (t < 32) {
        int acc = 0;
        for (int i = t; i < b; i += 32) acc += g_bsum[i];
#pragma unroll
        for (int o = 16; o; o >>= 1) acc += __shfl_xor_sync(0xffffffffu, acc, o);
        if (t == 0) soff = acc;
    }
    __syncthreads();
    int off = soff;
    int base = b * SCAN_E + t * 4;
#pragma unroll
    for (int i = 0; i < 4; i++) {
        int idx = base + i;
        if (idx < NN) {
            int r = g_rowptr[idx] + off;
            g_rowptr[idx] = r;
            g_cursor[idx] = r;
        }
    }
    if (b == 0 && t == 0) g_rowptr[NN] = EE;
}

__global__ void k_scatter(const int* __restrict__ src, const int* __restrict__ dst) {
    int e = blockIdx.x * blockDim.x + threadIdx.x;
    if (e < EE) {
        int pos = atomicAdd(&g_cursor[dst[e]], 1);
        g_col[pos] = src[e];
    }
}

// ---------------- GEMM pass over one K=64 half (fp16 operands, f32x2 FMA) -------
__device__ __forceinline__ void gemm_pass(
    const __half* __restrict__ A, const __half* __restrict__ Wh,
    ull acc2[8][4], __half As[8][128], __half Bs[8][128],
    int grow, int arow, int ako, int bk, int bc, int cb, int row0, int col0) {

    uint2 av = make_uint2(0u, 0u);
    if (grow < NN) av = *(const uint2*)(A + grow * 64 + ako);
    uint2 bv = *(const uint2*)(Wh + bk * 256 + cb + bc);

    for (int kc = 0; kc < 64; kc += 8) {
        {
            const __half* ah = (const __half*)&av;
            As[ako + 0][arow] = ah[0];
            As[ako + 1][arow] = ah[1];
            As[ako + 2][arow] = ah[2];
            As[ako + 3][arow] = ah[3];
            *(uint2*)&Bs[bk][bc] = bv;
        }
        __syncthreads();
        if (kc < 56) {
            int kn = kc + 8;
            av = make_uint2(0u, 0u);
            if (grow < NN) av = *(const uint2*)(A + grow * 64 + kn + ako);
            bv = *(const uint2*)(Wh + (kn + bk) * 256 + cb + bc);
        }
#pragma unroll
        for (int k2 = 0; k2 < 8; k2++) {
            uint4 ar = *(const uint4*)&As[k2][row0];
            uint4 br = *(const uint4*)&Bs[k2][col0];
            const __half2* ah2 = (const __half2*)&ar;
            const __half2* bh2 = (const __half2*)&br;
            ull bd[4];
#pragma unroll
            for (int j2 = 0; j2 < 4; j2++) bd[j2] = packf2(__half22float2(bh2[j2]));
#pragma unroll
            for (int i2 = 0; i2 < 4; i2++) {
                float2 af = __half22float2(ah2[i2]);
                ull a0 = dupf2(af.x);
                ull a1 = dupf2(af.y);
#pragma unroll
                for (int j2 = 0; j2 < 4; j2++) fma2(acc2[i2 * 2 + 0][j2], a0, bd[j2]);
#pragma unroll
                for (int j2 = 0; j2 < 4; j2++) fma2(acc2[i2 * 2 + 1][j2], a1, bd[j2]);
            }
        }
        __syncthreads();
    }
}

// mode 0: FUSED: pass1 W[64:] -> C -> g_cs/g_cd; pass2 W[:64] (continue acc)
//         -> fs/fd = acc+bias.                                [layer 0]
// mode 2: fs/fd = h @ W[:64] + (g_cs|g_cd)                    [layers 1..3]
__global__ __launch_bounds__(256, 2)
void k_gemm(int mode, const float* __restrict__ bsrc, const float* __restrict__ bdst) {
    __shared__ __align__(16) __half As[8][128];
    __shared__ __align__(16) __half Bs[8][128];

    const __half* A = (mode == 2) ? g_hh : g_h0h;

    int m0 = blockIdx.x * 128;
    int n0 = blockIdx.y * 128;
    int is_src = (n0 < 256);
    const __half* Wh  = is_src ? g_wsh : g_wdh;
    const float* Cm   = is_src ? g_cs : g_cd;
    const float* bias = is_src ? bsrc : bdst;
    int cb = n0 & 255;

    int t    = threadIdx.x;
    int lane = t & 31, wid = t >> 5;
    int row0 = (wid & 3) * 32 + (lane >> 3) * 8;
    int col0 = (wid >> 2) * 64 + (lane & 7) * 8;

    int arow = t >> 1;
    int ako  = (t & 1) << 2;
    int grow = m0 + arow;
    int bk = t >> 5;
    int bc = (t & 31) << 2;

    ull acc2[8][4];
#pragma unroll
    for (int i = 0; i < 8; i++)
#pragma unroll
        for (int j = 0; j < 4; j++) acc2[i][j] = 0ULL;

    float bb[8];
#pragma unroll
    for (int j = 0; j < 8; j++) bb[j] = bias[cb + col0 + j];

    if (mode == 0) {
        gemm_pass(A, Wh + 64 * 256, acc2, As, Bs, grow, arow, ako, bk, bc, cb, row0, col0);
        {
            float* Out = is_src ? g_cs : g_cd;
#pragma unroll
            for (int i = 0; i < 8; i++) {
                int r = m0 + row0 + i;
                if (r < NN) {
                    float2 p0 = unpackf2(acc2[i][0]);
                    float2 p1 = unpackf2(acc2[i][1]);
                    float2 p2 = unpackf2(acc2[i][2]);
                    float2 p3 = unpackf2(acc2[i][3]);
                    float4 o0 = make_float4(p0.x + bb[0], p0.y + bb[1], p1.x + bb[2], p1.y + bb[3]);
                    float4 o1 = make_float4(p2.x + bb[4], p2.y + bb[5], p3.x + bb[6], p3.y + bb[7]);
                    *(float4*)&Out[(size_t)r * 256 + cb + col0]     = o0;
                    *(float4*)&Out[(size_t)r * 256 + cb + col0 + 4] = o1;
                }
            }
        }
        gemm_pass(A, Wh, acc2, As, Bs, grow, arow, ako, bk, bc, cb, row0, col0);
    } else {
        gemm_pass(A, Wh, acc2, As, Bs, grow, arow, ako, bk, bc, cb, row0, col0);
    }

#pragma unroll
    for (int i = 0; i < 8; i++) {
        int r = m0 + row0 + i;
        if (r >= NN) continue;
        float2 p0 = unpackf2(acc2[i][0]);
        float2 p1 = unpackf2(acc2[i][1]);
        float2 p2 = unpackf2(acc2[i][2]);
        float2 p3 = unpackf2(acc2[i][3]);
        float v[8] = {p0.x, p0.y, p1.x, p1.y, p2.x, p2.y, p3.x, p3.y};
        if (mode == 0) {
#pragma unroll
            for (int j = 0; j < 8; j++) v[j] += bb[j];
        } else {
            const float* Cp = Cm + (size_t)r * 256 + cb + col0;
            float4 c0 = *(const float4*)Cp;
            float4 c1 = *(const float4*)(Cp + 4);
            v[0] += c0.x; v[1] += c0.y; v[2] += c0.z; v[3] += c0.w;
            v[4] += c1.x; v[5] += c1.y; v[6] += c1.z; v[7] += c1.w;
        }
        if (is_src) {
            uint4 pk;
            __half2* hp = (__half2*)&pk;
            hp[0] = __floats2half2_rn(v[0], v[1]);
            hp[1] = __floats2half2_rn(v[2], v[3]);
            hp[2] = __floats2half2_rn(v[4], v[5]);
            hp[3] = __floats2half2_rn(v[6], v[7]);
            g_fsh[(size_t)r * 32 + ((cb + col0) >> 3)] = pk;
        } else {
            float4 o0 = make_float4(v[0], v[1], v[2], v[3]);
            float4 o1 = make_float4(v[4], v[5], v[6], v[7]);
            *(float4*)&g_fd[(size_t)r * 256 + cb + col0]     = o0;
            *(float4*)&g_fd[(size_t)r * 256 + cb + col0 + 4] = o1;
        }
    }
}

// ---------------- edge stage: 2 nodes per warp, interleaved chains --------------
__device__ __forceinline__ void h8_to_f(const uint4& raw, float* f) {
    const __half2* hp = (const __half2*)&raw;
    float2 a = __half22float2(hp[0]);
    float2 b = __half22float2(hp[1]);
    float2 c = __half22float2(hp[2]);
    float2 d = __half22float2(hp[3]);
    f[0] = a.x; f[1] = a.y; f[2] = b.x; f[3] = b.y;
    f[4] = c.x; f[5] = c.y; f[6] = d.x; f[7] = d.y;
}

__global__ void k_edge(const float* __restrict__ attn, int last) {
    int w = (blockIdx.x * blockDim.x + threadIdx.x) >> 5;
    int gw0 = w * 2;
    if (gw0 >= NN) return;
    int gw1 = gw0 + 1;
    bool has1 = (gw1 < NN);
    int lane = threadIdx.x & 31;
    int base = lane << 3;

    float av[8];
    {
        float4 a0 = *(const float4*)&attn[base];
        float4 a1 = *(const float4*)&attn[base + 4];
        av[0] = a0.x; av[1] = a0.y; av[2] = a0.z; av[3] = a0.w;
        av[4] = a1.x; av[5] = a1.y; av[6] = a1.z; av[7] = a1.w;
    }
    float fdv0[8], fdv1[8];
    {
        float4 v0 = *(const float4*)&g_fd[(size_t)gw0 * 256 + base];
        float4 v1 = *(const float4*)&g_fd[(size_t)gw0 * 256 + base + 4];
        fdv0[0] = v0.x; fdv0[1] = v0.y; fdv0[2] = v0.z; fdv0[3] = v0.w;
        fdv0[4] = v1.x; fdv0[5] = v1.y; fdv0[6] = v1.z; fdv0[7] = v1.w;
    }
    if (has1) {
        float4 v0 = *(const float4*)&g_fd[(size_t)gw1 * 256 + base];
        float4 v1 = *(const float4*)&g_fd[(size_t)gw1 * 256 + base + 4];
        fdv1[0] = v0.x; fdv1[1] = v0.y; fdv1[2] = v0.z; fdv1[3] = v0.w;
        fdv1[4] = v1.x; fdv1[5] = v1.y; fdv1[6] = v1.z; fdv1[7] = v1.w;
    } else {
#pragma unroll
        for (int i = 0; i < 8; i++) fdv1[i] = 0.f;
    }

    int e0 = g_rowptr[gw0], end0 = g_rowptr[gw0 + 1];
    int e1 = has1 ? g_rowptr[gw1] : 0;
    int end1 = has1 ? g_rowptr[gw1 + 1] : 0;

    float acc0[8], acc1[8];
#pragma unroll
    for (int i = 0; i < 8; i++) { acc0[i] = 0.f; acc1[i] = 0.f; }
    float m0 = -CUDART_INF_F, s0 = 0.f;
    float m1 = -CUDART_INF_F, s1 = 0.f;

    while (e0 < end0 || e1 < end1) {
        bool a0 = (e0 < end0), a1 = (e1 < end1);   // warp-uniform
        int j0 = a0 ? g_col[e0] : 0;
        int j1 = a1 ? g_col[e1] : 0;
        uint4 r0 = g_fsh[(size_t)j0 * 32 + lane];
        uint4 r1 = g_fsh[(size_t)j1 * 32 + lane];
        float f0[8], f1[8];
        h8_to_f(r0, f0);
        h8_to_f(r1, f1);

        float p0 = 0.f, p1 = 0.f;
#pragma unroll
        for (int i = 0; i < 8; i++) {
            float y0 = f0[i] + fdv0[i]; y0 = (y0 > 0.f) ? y0 : 0.2f * y0;
            float y1 = f1[i] + fdv1[i]; y1 = (y1 > 0.f) ? y1 : 0.2f * y1;
            p0 += av[i] * y0;
            p1 += av[i] * y1;
        }
        p0 += __shfl_xor_sync(0xffffffffu, p0, 1);
        p1 += __shfl_xor_sync(0xffffffffu, p1, 1);
        p0 += __shfl_xor_sync(0xffffffffu, p0, 2);
        p1 += __shfl_xor_sync(0xffffffffu, p1, 2);
        p0 += __shfl_xor_sync(0xffffffffu, p0, 4);
        p1 += __shfl_xor_sync(0xffffffffu, p1, 4);

        if (a0) {
            float mn = fmaxf(m0, p0);
            float cold = __expf(m0 - mn);
            float wgt = __expf(p0 - mn);
            s0 = s0 * cold + wgt;
#pragma unroll
            for (int i = 0; i < 8; i++) acc0[i] = acc0[i] * cold + wgt * f0[i];
            m0 = mn;
            e0++;
        }
        if (a1) {
            float mn = fmaxf(m1, p1);
            float cold = __expf(m1 - mn);
            float wgt = __expf(p1 - mn);
            s1 = s1 * cold + wgt;
#pragma unroll
            for (int i = 0; i < 8; i++) acc1[i] = acc1[i] * cold + wgt * f1[i];
            m1 = mn;
            e1++;
        }
    }

    float inv0 = (end0 > g_rowptr[gw0]) ? (1.f / s0) : 0.f;
    float out0[8];
#pragma unroll
    for (int i = 0; i < 8; i++) {
        float r = tanhf(acc0[i] * inv0);
        r += __shfl_xor_sync(0xffffffffu, r, 8);
        r += __shfl_xor_sync(0xffffffffu, r, 16);
        out0[i] = r;
    }
    float inv1 = (has1 && end1 > g_rowptr[gw1]) ? (1.f / s1) : 0.f;
    float out1[8];
#pragma unroll
    for (int i = 0; i < 8; i++) {
        float r = tanhf(acc1[i] * inv1);
        r += __shfl_xor_sync(0xffffffffu, r, 8);
        r += __shfl_xor_sync(0xffffffffu, r, 16);
        out1[i] = r;
    }

    if (lane < 8) {
        if (last) {
            float4 o0 = make_float4(out0[0], out0[1], out0[2], out0[3]);
            float4 o1 = make_float4(out0[4], out0[5], out0[6], out0[7]);
            *(float4*)&g_h[(size_t)gw0 * 64 + base]     = o0;
            *(float4*)&g_h[(size_t)gw0 * 64 + base + 4] = o1;
            if (has1) {
                float4 q0 = make_float4(out1[0], out1[1], out1[2], out1[3]);
                float4 q1 = make_float4(out1[4], out1[5], out1[6], out1[7]);
                *(float4*)&g_h[(size_t)gw1 * 64 + base]     = q0;
                *(float4*)&g_h[(size_t)gw1 * 64 + base + 4] = q1;
            }
        } else {
            uint4 pk;
            __half2* hp = (__half2*)&pk;
            hp[0] = __floats2half2_rn(out0[0], out0[1]);
            hp[1] = __floats2half2_rn(out0[2], out0[3]);
            hp[2] = __floats2half2_rn(out0[4], out0[5]);
            hp[3] = __floats2half2_rn(out0[6], out0[7]);
            *(uint4*)&g_hh[(size_t)gw0 * 64 + base] = pk;
            if (has1) {
                uint4 pk1;
                __half2* hq = (__half2*)&pk1;
                hq[0] = __floats2half2_rn(out1[0], out1[1]);
                hq[1] = __floats2half2_rn(out1[2], out1[3]);
                hq[2] = __floats2half2_rn(out1[4], out1[5]);
                hq[3] = __floats2half2_rn(out1[6], out1[7]);
                *(uint4*)&g_hh[(size_t)gw1 * 64 + base] = pk1;
            }
        }
    }
}

// ---------------- graph readout: run-length accumulate (gid is sorted) ----------
__global__ void k_readout(const float* __restrict__ is_root, const int* __restrict__ gid) {
    __shared__ float sh[BB * 64];
    for (int i = threadIdx.x; i < BB * 64; i += blockDim.x) sh[i] = 0.f;
    __syncthreads();
    int npb = (NN + gridDim.x - 1) / gridDim.x;
    int n0 = blockIdx.x * npb;
    int n1 = min(n0 + npb, NN);
    int d = threadIdx.x & 63;
    int slot = threadIdx.x >> 6;
    float racc = 0.f;
    int rgid = -1;
    for (int n = n0 + slot; n < n1; n += (blockDim.x >> 6)) {
        int g = gid[n];
        if (g != rgid) {
            if (rgid >= 0) atomicAdd(&sh[rgid * 64 + d], racc);
            racc = 0.f;
            rgid = g;
        }
        racc += g_h[n * 64 + d] * is_root[n];
    }
    if (rgid >= 0) atomicAdd(&sh[rgid * 64 + d], racc);
    __syncthreads();
    for (int i = threadIdx.x; i < BB * 64; i += blockDim.x) {
        float v = sh[i];
        if (v != 0.f) atomicAdd(&g_hg[i], v);
    }
}

// ---------------- out = hg @ W_out + b_out ----------------
__global__ void k_out(const float* __restrict__ Wout, const float* __restrict__ bout,
                      float* __restrict__ out) {
    int t = threadIdx.x;
    if (t >= BB * 32) return;
    int b = t >> 5, o = t & 31;
    float s = bout[o];
#pragma unroll
    for (int d = 0; d < 64; d++) s += g_hg[b * 64 + d] * Wout[d * 32 + o];
    out[t] = s;
}

// ---------------- launch ----------------
extern "C" void kernel_launch(void* const* d_in, const int* in_sizes, int n_in,
                              void* d_out, int out_size) {
    const float* feat    = (const float*)d_in[0];
    const float* is_root = (const float*)d_in[1];
    const int*   src     = (const int*)d_in[2];
    const int*   dst     = (const int*)d_in[3];
    const int*   gid     = (const int*)d_in[4];
    const float* W_in    = (const float*)d_in[5];
    const float* b_in    = (const float*)d_in[6];
    const float* W_src   = (const float*)d_in[7];
    const float* b_src   = (const float*)d_in[8];
    const float* W_dst   = (const float*)d_in[9];
    const float* b_dst   = (const float*)d_in[10];
    const float* attn    = (const float*)d_in[11];
    const float* W_out   = (const float*)d_in[12];
    const float* b_out   = (const float*)d_in[13];
    float* out = (float*)d_out;

    dim3 ggrid(GM, 4);
    int eblocks = ((NN + 1) / 2 * 32 + 255) / 256;

    k_in<<<(NN * 64 + 255) / 256, 256>>>(feat, W_in, b_in, W_src, W_dst);
    k_hist<<<(EE + 255) / 256, 256>>>(dst);
    k_scan1<<<SCAN_NB, 256>>>();

    // position 4 (profiled): FUSED precompute + layer-0 GEMM (K=128)
    k_gemm<<<ggrid, 256>>>(0, b_src, b_dst);

    k_scan3<<<SCAN_NB, 256>>>();
    k_scatter<<<(EE + 255) / 256, 256>>>(src, dst);

    k_edge<<<eblocks, 256>>>(attn, 0);   // layer 0

    for (int layer = 1; layer < 4; layer++) {
        k_gemm<<<ggrid, 256>>>(2, b_src, b_dst);
        k_edge<<<eblocks, 256>>>(attn, layer == 3 ? 1 : 0);
    }

    k_readout<<<256, 256>>>(is_root, gid);
    k_out<<<1, 512>>>(W_out, b_out, out);
}

// round 16
// speedup vs baseline: 1.0983x; 1.0983x over previous
#include <cuda_runtime.h>
#include <cuda_fp16.h>
#include <math_constants.h>
#include <cstdint>

#define NN 50000
#define EE 400000
#define BB 16
#define SCAN_E 1024
#define SCAN_NB ((NN + SCAN_E - 1) / SCAN_E)  // 49
#define GM ((NN + 127) / 128)                 // 391 M-tiles

typedef unsigned long long ull;

// ---------------- scratch (static device globals; no allocation) ----------------
__device__ __half g_h0h[NN * 64];   // h0 in fp16 (GEMM A operand)
__device__ __half g_hh [NN * 64];   // h  in fp16 (GEMM A operand)
__device__ float  g_h  [NN * 64];   // h  in fp32 (readout, last layer only)
__device__ __half g_wsh[128 * 256]; // W_src fp16
__device__ __half g_wdh[128 * 256]; // W_dst fp16
__device__ uint4  g_fsh[NN * 32];   // fs as fp16: 256 halves = 32 uint4 per node
__device__ float  g_fd [NN * 256];
__device__ float  g_cs [NN * 256];  // h0 @ W_src[64:] + b_src   (layer-invariant)
__device__ float  g_cd [NN * 256];  // h0 @ W_dst[64:] + b_dst
__device__ int    g_rowptr[NN + 1];
__device__ int    g_cursor[NN];
__device__ int    g_counts[NN];
__device__ int    g_col[EE];
__device__ int    g_bsum[SCAN_NB];
__device__ float  g_hg[BB * 64];

// ---------------- packed f32x2 helpers ----------------
__device__ __forceinline__ void fma2(ull& d, ull a, ull b) {
    asm("fma.rn.f32x2 %0, %1, %2, %0;" : "+l"(d) : "l"(a), "l"(b));
}
__device__ __forceinline__ ull dupf2(float v) {
    ull r; uint32_t u = __float_as_uint(v);
    asm("mov.b64 %0, {%1, %1};" : "=l"(r) : "r"(u));
    return r;
}
__device__ __forceinline__ ull packf2(float2 v) {
    ull r;
    asm("mov.b64 %0, {%1, %2};" : "=l"(r) : "f"(v.x), "f"(v.y));
    return r;
}
__device__ __forceinline__ float2 unpackf2(ull v) {
    float lo, hi;
    asm("mov.b64 {%0, %1}, %2;" : "=f"(lo), "=f"(hi) : "l"(v));
    return make_float2(lo, hi);
}

// ---- h0 = feat @ W_in + b_in (fp16 out) + zero hg + convert W to fp16 ----------
// NOTE: g_counts is zeroed on the side stream (k_zero), NOT here (race with hist)
__global__ void k_in(const float* __restrict__ feat, const float* __restrict__ Win,
                     const float* __restrict__ bin,
                     const float* __restrict__ Wsrc, const float* __restrict__ Wdst) {
    int idx = blockIdx.x * blockDim.x + threadIdx.x;
    if (idx < BB * 64) g_hg[idx] = 0.f;
    if (idx < 128 * 256) {
        g_wsh[idx] = __float2half(Wsrc[idx]);
        g_wdh[idx] = __float2half(Wdst[idx]);
    }
    if (idx >= NN * 64) return;
    int n = idx >> 6, d = idx & 63;
    float s = bin[d];
#pragma unroll
    for (int k = 0; k < 16; k++) s += feat[n * 16 + k] * Win[k * 64 + d];
    g_h0h[idx] = __float2half(s);
}

// ---------------- CSR build (keyed by dst) -- runs on side stream ----------------
__global__ void k_zero() {
    int i = blockIdx.x * blockDim.x + threadIdx.x;
    if (i < NN) g_counts[i] = 0;
}

__global__ void k_hist(const int* __restrict__ dst) {
    int e = blockIdx.x * blockDim.x + threadIdx.x;
    if (e < EE) atomicAdd(&g_counts[dst[e]], 1);
}

__global__ void k_scan1() {
    __shared__ int ws[8];
    int t = threadIdx.x, b = blockIdx.x;
    int base = b * SCAN_E + t * 4;
    int v0 = 0, v1 = 0, v2 = 0, v3 = 0;
    if (base + 0 < NN) v0 = g_counts[base + 0];
    if (base + 1 < NN) v1 = g_counts[base + 1];
    if (base + 2 < NN) v2 = g_counts[base + 2];
    if (base + 3 < NN) v3 = g_counts[base + 3];
    int s = v0 + v1 + v2 + v3;
    int lane = t & 31, wid = t >> 5;
    int x = s;
#pragma unroll
    for (int o = 1; o < 32; o <<= 1) {
        int u = __shfl_up_sync(0xffffffffu, x, o);
        if (lane >= o) x += u;
    }
    if (lane == 31) ws[wid] = x;
    __syncthreads();
    if (wid == 0 && lane < 8) {
        int w = ws[lane];
#pragma unroll
        for (int o = 1; o < 8; o <<= 1) {
            int u = __shfl_up_sync(0x000000ffu, w, o);
            if (lane >= o) w += u;
        }
        ws[lane] = w;
    }
    __syncthreads();
    int excl = (x - s) + (wid > 0 ? ws[wid - 1] : 0);
    int run = excl;
    if (base + 0 < NN) { g_rowptr[base + 0] = run; run += v0; }
    if (base + 1 < NN) { g_rowptr[base + 1] = run; run += v1; }
    if (base + 2 < NN) { g_rowptr[base + 2] = run; run += v2; }
    if (base + 3 < NN) { g_rowptr[base + 3] = run; run += v3; }
    if (t == blockDim.x - 1) g_bsum[b] = excl + s;
}

__global__ void k_scan3() {
    __shared__ int soff;
    int t = threadIdx.x, b = blockIdx.x;
    if (t < 32) {
        int acc = 0;
        for (int i = t; i < b; i += 32) acc += g_bsum[i];
#pragma unroll
        for (int o = 16; o; o >>= 1) acc += __shfl_xor_sync(0xffffffffu, acc, o);
        if (t == 0) soff = acc;
    }
    __syncthreads();
    int off = soff;
    int base = b * SCAN_E + t * 4;
#pragma unroll
    for (int i = 0; i < 4; i++) {
        int idx = base + i;
        if (idx < NN) {
            int r = g_rowptr[idx] + off;
            g_rowptr[idx] = r;
            g_cursor[idx] = r;
        }
    }
    if (b == 0 && t == 0) g_rowptr[NN] = EE;
}

__global__ void k_scatter(const int* __restrict__ src, const int* __restrict__ dst) {
    int e = blockIdx.x * blockDim.x + threadIdx.x;
    if (e < EE) {
        int pos = atomicAdd(&g_cursor[dst[e]], 1);
        g_col[pos] = src[e];
    }
}

// ---------------- GEMM pass over one K=64 half (fp16 operands, f32x2 FMA) -------
__device__ __forceinline__ void gemm_pass(
    const __half* __restrict__ A, const __half* __restrict__ Wh,
    ull acc2[8][4], __half As[8][128], __half Bs[8][128],
    int grow, int arow, int ako, int bk, int bc, int cb, int row0, int col0) {

    uint2 av = make_uint2(0u, 0u);
    if (grow < NN) av = *(const uint2*)(A + grow * 64 + ako);
    uint2 bv = *(const uint2*)(Wh + bk * 256 + cb + bc);

    for (int kc = 0; kc < 64; kc += 8) {
        {
            const __half* ah = (const __half*)&av;
            As[ako + 0][arow] = ah[0];
            As[ako + 1][arow] = ah[1];
            As[ako + 2][arow] = ah[2];
            As[ako + 3][arow] = ah[3];
            *(uint2*)&Bs[bk][bc] = bv;
        }
        __syncthreads();
        if (kc < 56) {
            int kn = kc + 8;
            av = make_uint2(0u, 0u);
            if (grow < NN) av = *(const uint2*)(A + grow * 64 + kn + ako);
            bv = *(const uint2*)(Wh + (kn + bk) * 256 + cb + bc);
        }
#pragma unroll
        for (int k2 = 0; k2 < 8; k2++) {
            uint4 ar = *(const uint4*)&As[k2][row0];
            uint4 br = *(const uint4*)&Bs[k2][col0];
            const __half2* ah2 = (const __half2*)&ar;
            const __half2* bh2 = (const __half2*)&br;
            ull bd[4];
#pragma unroll
            for (int j2 = 0; j2 < 4; j2++) bd[j2] = packf2(__half22float2(bh2[j2]));
#pragma unroll
            for (int i2 = 0; i2 < 4; i2++) {
                float2 af = __half22float2(ah2[i2]);
                ull a0 = dupf2(af.x);
                ull a1 = dupf2(af.y);
#pragma unroll
                for (int j2 = 0; j2 < 4; j2++) fma2(acc2[i2 * 2 + 0][j2], a0, bd[j2]);
#pragma unroll
                for (int j2 = 0; j2 < 4; j2++) fma2(acc2[i2 * 2 + 1][j2], a1, bd[j2]);
            }
        }
        __syncthreads();
    }
}

// mode 0: FUSED: pass1 W[64:] -> C -> g_cs/g_cd; pass2 W[:64] (continue acc)
//         -> fs/fd = acc+bias.                                [layer 0]
// mode 2: fs/fd = h @ W[:64] + (g_cs|g_cd)                    [layers 1..3]
__global__ __launch_bounds__(256, 2)
void k_gemm(int mode, const float* __restrict__ bsrc, const float* __restrict__ bdst) {
    __shared__ __align__(16) __half As[8][128];
    __shared__ __align__(16) __half Bs[8][128];

    const __half* A = (mode == 2) ? g_hh : g_h0h;

    int m0 = blockIdx.x * 128;
    int n0 = blockIdx.y * 128;
    int is_src = (n0 < 256);
    const __half* Wh  = is_src ? g_wsh : g_wdh;
    const float* Cm   = is_src ? g_cs : g_cd;
    const float* bias = is_src ? bsrc : bdst;
    int cb = n0 & 255;

    int t    = threadIdx.x;
    int lane = t & 31, wid = t >> 5;
    int row0 = (wid & 3) * 32 + (lane >> 3) * 8;
    int col0 = (wid >> 2) * 64 + (lane & 7) * 8;

    int arow = t >> 1;
    int ako  = (t & 1) << 2;
    int grow = m0 + arow;
    int bk = t >> 5;
    int bc = (t & 31) << 2;

    ull acc2[8][4];
#pragma unroll
    for (int i = 0; i < 8; i++)
#pragma unroll
        for (int j = 0; j < 4; j++) acc2[i][j] = 0ULL;

    float bb[8];
#pragma unroll
    for (int j = 0; j < 8; j++) bb[j] = bias[cb + col0 + j];

    if (mode == 0) {
        gemm_pass(A, Wh + 64 * 256, acc2, As, Bs, grow, arow, ako, bk, bc, cb, row0, col0);
        {
            float* Out = is_src ? g_cs : g_cd;
#pragma unroll
            for (int i = 0; i < 8; i++) {
                int r = m0 + row0 + i;
                if (r < NN) {
                    float2 p0 = unpackf2(acc2[i][0]);
                    float2 p1 = unpackf2(acc2[i][1]);
                    float2 p2 = unpackf2(acc2[i][2]);
                    float2 p3 = unpackf2(acc2[i][3]);
                    float4 o0 = make_float4(p0.x + bb[0], p0.y + bb[1], p1.x + bb[2], p1.y + bb[3]);
                    float4 o1 = make_float4(p2.x + bb[4], p2.y + bb[5], p3.x + bb[6], p3.y + bb[7]);
                    *(float4*)&Out[(size_t)r * 256 + cb + col0]     = o0;
                    *(float4*)&Out[(size_t)r * 256 + cb + col0 + 4] = o1;
                }
            }
        }
        gemm_pass(A, Wh, acc2, As, Bs, grow, arow, ako, bk, bc, cb, row0, col0);
    } else {
        gemm_pass(A, Wh, acc2, As, Bs, grow, arow, ako, bk, bc, cb, row0, col0);
    }

#pragma unroll
    for (int i = 0; i < 8; i++) {
        int r = m0 + row0 + i;
        if (r >= NN) continue;
        float2 p0 = unpackf2(acc2[i][0]);
        float2 p1 = unpackf2(acc2[i][1]);
        float2 p2 = unpackf2(acc2[i][2]);
        float2 p3 = unpackf2(acc2[i][3]);
        float v[8] = {p0.x, p0.y, p1.x, p1.y, p2.x, p2.y, p3.x, p3.y};
        if (mode == 0) {
#pragma unroll
            for (int j = 0; j < 8; j++) v[j] += bb[j];
        } else {
            const float* Cp = Cm + (size_t)r * 256 + cb + col0;
            float4 c0 = *(const float4*)Cp;
            float4 c1 = *(const float4*)(Cp + 4);
            v[0] += c0.x; v[1] += c0.y; v[2] += c0.z; v[3] += c0.w;
            v[4] += c1.x; v[5] += c1.y; v[6] += c1.z; v[7] += c1.w;
        }
        if (is_src) {
            uint4 pk;
            __half2* hp = (__half2*)&pk;
            hp[0] = __floats2half2_rn(v[0], v[1]);
            hp[1] = __floats2half2_rn(v[2], v[3]);
            hp[2] = __floats2half2_rn(v[4], v[5]);
            hp[3] = __floats2half2_rn(v[6], v[7]);
            g_fsh[(size_t)r * 32 + ((cb + col0) >> 3)] = pk;
        } else {
            float4 o0 = make_float4(v[0], v[1], v[2], v[3]);
            float4 o1 = make_float4(v[4], v[5], v[6], v[7]);
            *(float4*)&g_fd[(size_t)r * 256 + cb + col0]     = o0;
            *(float4*)&g_fd[(size_t)r * 256 + cb + col0 + 4] = o1;
        }
    }
}

// ---------------- edge stage: one warp/node, fp16 gather, simple loop -----------
__device__ __forceinline__ void h8_to_f(const uint4& raw, float* f) {
    const __half2* hp = (const __half2*)&raw;
    float2 a = __half22float2(hp[0]);
    float2 b = __half22float2(hp[1]);
    float2 c = __half22float2(hp[2]);
    float2 d = __half22float2(hp[3]);
    f[0] = a.x; f[1] = a.y; f[2] = b.x; f[3] = b.y;
    f[4] = c.x; f[5] = c.y; f[6] = d.x; f[7] = d.y;
}

__global__ void k_edge(const float* __restrict__ attn, int last) {
    int gw = (blockIdx.x * blockDim.x + threadIdx.x) >> 5;
    if (gw >= NN) return;
    int lane = threadIdx.x & 31;
    int base = lane << 3;

    int beg = g_rowptr[gw];
    int end = g_rowptr[gw + 1];

    float fdv[8], av[8], acc[8];
    {
        float4 v0 = *(const float4*)&g_fd[(size_t)gw * 256 + base];
        float4 v1 = *(const float4*)&g_fd[(size_t)gw * 256 + base + 4];
        fdv[0] = v0.x; fdv[1] = v0.y; fdv[2] = v0.z; fdv[3] = v0.w;
        fdv[4] = v1.x; fdv[5] = v1.y; fdv[6] = v1.z; fdv[7] = v1.w;
        float4 a0 = *(const float4*)&attn[base];
        float4 a1 = *(const float4*)&attn[base + 4];
        av[0] = a0.x; av[1] = a0.y; av[2] = a0.z; av[3] = a0.w;
        av[4] = a1.x; av[5] = a1.y; av[6] = a1.z; av[7] = a1.w;
    }
#pragma unroll
    for (int i = 0; i < 8; i++) acc[i] = 0.f;
    float m = -CUDART_INF_F, sden = 0.f;

    for (int e = beg; e < end; e++) {
        int j = g_col[e];
        uint4 rr = g_fsh[(size_t)j * 32 + lane];
        float fv[8];
        h8_to_f(rr, fv);
        float p = 0.f;
#pragma unroll
        for (int i = 0; i < 8; i++) {
            float x = fv[i] + fdv[i];
            x = (x > 0.f) ? x : 0.2f * x;   // LeakyReLU(0.2)
            p += av[i] * x;
        }
        p += __shfl_xor_sync(0xffffffffu, p, 1);
        p += __shfl_xor_sync(0xffffffffu, p, 2);
        p += __shfl_xor_sync(0xffffffffu, p, 4);  // per-head logit
        float mn = fmaxf(m, p);
        float cold = __expf(m - mn);
        float w = __expf(p - mn);
        sden = sden * cold + w;
#pragma unroll
        for (int i = 0; i < 8; i++) acc[i] = acc[i] * cold + w * fv[i];
        m = mn;
    }

    float inv = (end > beg) ? (1.f / sden) : 0.f;
    float out[8];
#pragma unroll
    for (int i = 0; i < 8; i++) {
        float r = tanhf(acc[i] * inv);
        r += __shfl_xor_sync(0xffffffffu, r, 8);
        r += __shfl_xor_sync(0xffffffffu, r, 16);  // sum over 4 heads
        out[i] = r;
    }
    if (lane < 8) {
        if (last) {
            float4 o0 = make_float4(out[0], out[1], out[2], out[3]);
            float4 o1 = make_float4(out[4], out[5], out[6], out[7]);
            *(float4*)&g_h[(size_t)gw * 64 + base]     = o0;
            *(float4*)&g_h[(size_t)gw * 64 + base + 4] = o1;
        } else {
            uint4 pk;
            __half2* hp = (__half2*)&pk;
            hp[0] = __floats2half2_rn(out[0], out[1]);
            hp[1] = __floats2half2_rn(out[2], out[3]);
            hp[2] = __floats2half2_rn(out[4], out[5]);
            hp[3] = __floats2half2_rn(out[6], out[7]);
            *(uint4*)&g_hh[(size_t)gw * 64 + base] = pk;
        }
    }
}

// ---------------- graph readout: run-length accumulate (gid is sorted) ----------
__global__ void k_readout(const float* __restrict__ is_root, const int* __restrict__ gid) {
    __shared__ float sh[BB * 64];
    for (int i = threadIdx.x; i < BB * 64; i += blockDim.x) sh[i] = 0.f;
    __syncthreads();
    int npb = (NN + gridDim.x - 1) / gridDim.x;
    int n0 = blockIdx.x * npb;
    int n1 = min(n0 + npb, NN);
    int d = threadIdx.x & 63;
    int slot = threadIdx.x >> 6;
    float racc = 0.f;
    int rgid = -1;
    for (int n = n0 + slot; n < n1; n += (blockDim.x >> 6)) {
        int g = gid[n];
        if (g != rgid) {
            if (rgid >= 0) atomicAdd(&sh[rgid * 64 + d], racc);
            racc = 0.f;
            rgid = g;
        }
        racc += g_h[n * 64 + d] * is_root[n];
    }
    if (rgid >= 0) atomicAdd(&sh[rgid * 64 + d], racc);
    __syncthreads();
    for (int i = threadIdx.x; i < BB * 64; i += blockDim.x) {
        float v = sh[i];
        if (v != 0.f) atomicAdd(&g_hg[i], v);
    }
}

// ---------------- out = hg @ W_out + b_out ----------------
__global__ void k_out(const float* __restrict__ Wout, const float* __restrict__ bout,
                      float* __restrict__ out) {
    int t = threadIdx.x;
    if (t >= BB * 32) return;
    int b = t >> 5, o = t & 31;
    float s = bout[o];
#pragma unroll
    for (int d = 0; d < 64; d++) s += g_hg[b * 64 + d] * Wout[d * 32 + o];
    out[t] = s;
}

// ---------------- launch ----------------
extern "C" void kernel_launch(void* const* d_in, const int* in_sizes, int n_in,
                              void* d_out, int out_size) {
    const float* feat    = (const float*)d_in[0];
    const float* is_root = (const float*)d_in[1];
    const int*   src     = (const int*)d_in[2];
    const int*   dst     = (const int*)d_in[3];
    const int*   gid     = (const int*)d_in[4];
    const float* W_in    = (const float*)d_in[5];
    const float* b_in    = (const float*)d_in[6];
    const float* W_src   = (const float*)d_in[7];
    const float* b_src   = (const float*)d_in[8];
    const float* W_dst   = (const float*)d_in[9];
    const float* b_dst   = (const float*)d_in[10];
    const float* attn    = (const float*)d_in[11];
    const float* W_out   = (const float*)d_in[12];
    const float* b_out   = (const float*)d_in[13];
    float* out = (float*)d_out;

    // Side stream + events, created once on the first (uncaptured) call.
    static cudaStream_t s2 = []() {
        cudaStream_t s;
        cudaStreamCreateWithFlags(&s, cudaStreamNonBlocking);
        return s;
    }();
    static cudaEvent_t ev_fork = []() {
        cudaEvent_t e;
        cudaEventCreateWithFlags(&e, cudaEventDisableTiming);
        return e;
    }();
    static cudaEvent_t ev_join = []() {
        cudaEvent_t e;
        cudaEventCreateWithFlags(&e, cudaEventDisableTiming);
        return e;
    }();

    dim3 ggrid(GM, 4);
    int eblocks = (NN * 32 + 255) / 256;

    // fork: CSR chain on side stream (depends only on src/dst inputs)
    cudaEventRecord(ev_fork, 0);
    cudaStreamWaitEvent(s2, ev_fork, 0);
    k_zero<<<(NN + 255) / 256, 256, 0, s2>>>();
    k_hist<<<(EE + 255) / 256, 256, 0, s2>>>(dst);
    k_scan1<<<SCAN_NB, 256, 0, s2>>>();
    k_scan3<<<SCAN_NB, 256, 0, s2>>>();
    k_scatter<<<(EE + 255) / 256, 256, 0, s2>>>(src, dst);
    cudaEventRecord(ev_join, s2);

    // main stream: input transform + fused precompute/layer-0 GEMM (K=128)
    k_in<<<(NN * 64 + 255) / 256, 256>>>(feat, W_in, b_in, W_src, W_dst);
    k_gemm<<<ggrid, 256>>>(0, b_src, b_dst);

    // join before the first edge pass (needs CSR + gemm results)
    cudaStreamWaitEvent(0, ev_join, 0);

    k_edge<<<eblocks, 256>>>(attn, 0);   // layer 0

    for (int layer = 1; layer < 4; layer++) {
        k_gemm<<<ggrid, 256>>>(2, b_src, b_dst);
        k_edge<<<eblocks, 256>>>(attn, layer == 3 ? 1 : 0);
    }

    k_readout<<<256, 256>>>(is_root, gid);
    k_out<<<1, 512>>>(W_out, b_out, out);
}